// round 7
// baseline (speedup 1.0000x reference)
#include <cuda_runtime.h>
#include <stdint.h>

#define N_ENT 4096
#define FDIM  512
#define CELLS 39
#define PAIRS 8192

// ---------------- scratch (device globals: allocation-free rule) ----------------
__device__ int8_t g_A1[N_ENT * FDIM];                       // 2 MB   round(E/sA)
__device__ int8_t g_A2[N_ENT * FDIM];                       // 2 MB   round(256*residual)
__device__ float  g_sA[N_ENT];
__device__ int8_t g_B1[(size_t)CELLS * FDIM * FDIM];        // 10 MB  [c][kout][n]
__device__ int8_t g_B2[(size_t)CELLS * FDIM * FDIM];        // 10 MB
__device__ float  g_sBw[CELLS * FDIM];                      // sB * wl[c,kout]
__device__ float  g_Wt[FDIM * FDIM];                        // W transposed [kout][n]
__device__ float  g_T[(size_t)CELLS * N_ENT * FDIM];        // 327 MB T'_c

// ---------------- small helpers ----------------
__device__ __forceinline__ uint32_t smem_to_u32(const void* p) {
    uint32_t a;
    asm("{ .reg .u64 t; cvta.to.shared.u64 t, %1; cvt.u32.u64 %0, t; }" : "=r"(a) : "l"(p));
    return a;
}
__device__ __forceinline__ void cp_async16(uint32_t dst, const void* src) {
    asm volatile("cp.async.cg.shared.global [%0], [%1], 16;" :: "r"(dst), "l"(src));
}
#define CP_COMMIT() asm volatile("cp.async.commit_group;" ::: "memory")
#define CP_WAIT(n)  asm volatile("cp.async.wait_group %0;" :: "n"(n) : "memory")

#define LDSM_X4(r, addr) \
    asm volatile("ldmatrix.sync.aligned.m8n8.x4.shared.b16 {%0,%1,%2,%3}, [%4];" \
        : "=r"((r)[0]), "=r"((r)[1]), "=r"((r)[2]), "=r"((r)[3]) : "r"(addr))

__device__ __forceinline__ void imma16832(int* c, const uint32_t* a, uint32_t b0, uint32_t b1) {
    asm volatile("mma.sync.aligned.m16n8k32.row.col.s32.s8.s8.s32 "
                 "{%0,%1,%2,%3}, {%4,%5,%6,%7}, {%8,%9}, {%0,%1,%2,%3};"
                 : "+r"(c[0]), "+r"(c[1]), "+r"(c[2]), "+r"(c[3])
                 : "r"(a[0]), "r"(a[1]), "r"(a[2]), "r"(a[3]), "r"(b0), "r"(b1));
}

__device__ __forceinline__ int8_t clamp8(float x) {
    int i = __float2int_rn(x);
    i = i > 127 ? 127 : (i < -127 ? -127 : i);
    return (int8_t)i;
}

// ---------------- prep: transpose W ----------------
__global__ void prep_Wt(const float* __restrict__ W) {
    __shared__ float sW[32][33];
    int tx = threadIdx.x, ty = threadIdx.y;
    int n0 = blockIdx.y * 32, k0 = blockIdx.x * 32;
    sW[ty][tx] = W[(n0 + ty) * FDIM + (k0 + tx)];
    __syncthreads();
    g_Wt[(k0 + ty) * FDIM + (n0 + tx)] = sW[tx][ty];
}

// ---------------- prep: quantize E rows to 2-digit int8 ----------------
__global__ void __launch_bounds__(128) prep_E_q(const float* __restrict__ emb) {
    int row = blockIdx.x, t = threadIdx.x, lane = t & 31;
    float4 f = ((const float4*)(emb + (size_t)row * FDIM))[t];
    float m = fmaxf(fmaxf(fabsf(f.x), fabsf(f.y)), fmaxf(fabsf(f.z), fabsf(f.w)));
    #pragma unroll
    for (int o = 16; o; o >>= 1) m = fmaxf(m, __shfl_xor_sync(0xffffffffu, m, o));
    __shared__ float sm[4];
    if (lane == 0) sm[t >> 5] = m;
    __syncthreads();
    m = fmaxf(fmaxf(sm[0], sm[1]), fmaxf(sm[2], sm[3]));
    m = fmaxf(m, 1e-30f);
    if (t == 0) g_sA[row] = m / 127.f;
    float inv = 127.f / m;
    float v[4] = { f.x, f.y, f.z, f.w };
    char q1[4], q2[4];
    #pragma unroll
    for (int j = 0; j < 4; j++) {
        float q = v[j] * inv;
        float i1 = rintf(q);
        q1[j] = (char)(int)i1;
        q2[j] = (char)clamp8((q - i1) * 256.f);
    }
    *(char4*)(g_A1 + (size_t)row * FDIM + t * 4) = make_char4(q1[0], q1[1], q1[2], q1[3]);
    *(char4*)(g_A2 + (size_t)row * FDIM + t * 4) = make_char4(q2[0], q2[1], q2[2], q2[3]);
}

// ---------------- prep: quantize B rows (B[c][kout][n] = wl[c,n]*W[n,kout]) ----------------
__global__ void __launch_bounds__(128) prep_B_q(const float* __restrict__ wl) {
    int kout = blockIdx.x, c = blockIdx.y;
    int t = threadIdx.x, lane = t & 31;
    float4 w4 = ((const float4*)(g_Wt + (size_t)kout * FDIM))[t];
    float4 l4 = ((const float4*)(wl + (size_t)c * FDIM))[t];
    float v[4] = { w4.x * l4.x, w4.y * l4.y, w4.z * l4.z, w4.w * l4.w };
    float m = fmaxf(fmaxf(fabsf(v[0]), fabsf(v[1])), fmaxf(fabsf(v[2]), fabsf(v[3])));
    #pragma unroll
    for (int o = 16; o; o >>= 1) m = fmaxf(m, __shfl_xor_sync(0xffffffffu, m, o));
    __shared__ float sm[4];
    if (lane == 0) sm[t >> 5] = m;
    __syncthreads();
    m = fmaxf(fmaxf(sm[0], sm[1]), fmaxf(sm[2], sm[3]));
    m = fmaxf(m, 1e-30f);
    if (t == 0) g_sBw[c * FDIM + kout] = (m / 127.f) * __ldg(&wl[c * FDIM + kout]);
    float inv = 127.f / m;
    char q1[4], q2[4];
    #pragma unroll
    for (int j = 0; j < 4; j++) {
        float q = v[j] * inv;
        float i1 = rintf(q);
        q1[j] = (char)(int)i1;
        q2[j] = (char)clamp8((q - i1) * 256.f);
    }
    size_t off = ((size_t)c * FDIM + kout) * FDIM + t * 4;
    *(char4*)(g_B1 + off) = make_char4(q1[0], q1[1], q1[2], q1[3]);
    *(char4*)(g_B2 + off) = make_char4(q2[0], q2[1], q2[2], q2[3]);
}

// ---------------- GEMM: int8 2-digit Ozaki, T' = sA*sBw*(A1B1 + (A1B2+A2B1)/256) ----------
// CTA tile M=128, N=128, BK=64, 256 threads (8 warps: 2M x 4N, warp tile 64x32).
// SMEM tiles: 128 rows x 64B data, 80B stride (conflict-free ldmatrix, 80r mod 128 distinct).
#define BK        64
#define NKC       (FDIM / BK)      // 8
#define ROWB      80
#define TILE8     (128 * ROWB)     // 10240
#define T_A1      0
#define T_A2      (1 * TILE8)
#define T_B1      (2 * TILE8)
#define T_B2      (3 * TILE8)
#define BUF_BYTES (4 * TILE8)      // 40960
#define GEMM_SMEM (2 * BUF_BYTES)  // 81920

__device__ __forceinline__ void load_buf(uint32_t smem_u, int buf, int kc, int tid,
                                         const char* a1, const char* a2,
                                         const char* b1, const char* b2) {
    const char* srcs[4] = { a1, a2, b1, b2 };
    uint32_t dbase = smem_u + buf * BUF_BYTES;
    #pragma unroll
    for (int t = 0; t < 4; t++) {
        uint32_t dt = dbase + t * TILE8;
        const char* s = srcs[t] + (size_t)kc * BK;
        #pragma unroll
        for (int i = 0; i < 2; i++) {
            int v = i * 256 + tid;           // 0..511 : 128 rows x 4 segs of 16B
            int row = v >> 2, seg = v & 3;
            cp_async16(dt + row * ROWB + seg * 16,
                       s + (size_t)row * FDIM + seg * 16);
        }
    }
}

__global__ void __launch_bounds__(256, 1)
gemm_kernel(const float* __restrict__ dummy) {
    extern __shared__ char smem[];
    uint32_t smem_u = smem_to_u32(smem);

    const int tid = threadIdx.x;
    const int wid = tid >> 5, lane = tid & 31;
    const int warp_m = wid & 1;        // rows warp_m*64
    const int warp_n = wid >> 1;       // cols warp_n*32
    const int mt = blockIdx.x, nt = blockIdx.y, c = blockIdx.z;

    const char* a1 = (const char*)g_A1 + (size_t)(mt * 128) * FDIM;
    const char* a2 = (const char*)g_A2 + (size_t)(mt * 128) * FDIM;
    const char* b1 = (const char*)g_B1 + ((size_t)c * FDIM + nt * 128) * FDIM;
    const char* b2 = (const char*)g_B2 + ((size_t)c * FDIM + nt * 128) * FDIM;

    int accM[4][4][4], accC[4][4][4];
    #pragma unroll
    for (int i = 0; i < 4; i++)
        #pragma unroll
        for (int j = 0; j < 4; j++)
            #pragma unroll
            for (int q = 0; q < 4; q++) { accM[i][j][q] = 0; accC[i][j][q] = 0; }

    const int lr = lane & 15;
    const int lcb = (lane >> 4) * 16;

    load_buf(smem_u, 0, 0, tid, a1, a2, b1, b2);
    CP_COMMIT();

    for (int kc = 0; kc < NKC; kc++) {
        int buf = kc & 1;
        if (kc + 1 < NKC) {
            load_buf(smem_u, buf ^ 1, kc + 1, tid, a1, a2, b1, b2);
            CP_COMMIT();
            CP_WAIT(1);
        } else {
            CP_WAIT(0);
        }
        __syncthreads();

        uint32_t base = smem_u + buf * BUF_BYTES;
        uint32_t aOff = (warp_m * 64 + lr) * ROWB + lcb;
        uint32_t bOff = (warp_n * 32 + lr) * ROWB + lcb;

        #pragma unroll
        for (int ko2 = 0; ko2 < 2; ko2++) {
            uint32_t ko = ko2 * 32;    // 32 int8 = 32B per k32 step
            uint32_t A1f[4][4], A2f[4][4], B1f[2][4], B2f[2][4];
            #pragma unroll
            for (int mi = 0; mi < 4; mi++) {
                LDSM_X4(A1f[mi], base + T_A1 + aOff + mi * (16 * ROWB) + ko);
                LDSM_X4(A2f[mi], base + T_A2 + aOff + mi * (16 * ROWB) + ko);
            }
            #pragma unroll
            for (int nj = 0; nj < 2; nj++) {
                LDSM_X4(B1f[nj], base + T_B1 + bOff + nj * (16 * ROWB) + ko);
                LDSM_X4(B2f[nj], base + T_B2 + bOff + nj * (16 * ROWB) + ko);
            }
            #pragma unroll
            for (int mi = 0; mi < 4; mi++)
                #pragma unroll
                for (int n = 0; n < 4; n++) {
                    int nj = n >> 1, hf = n & 1;
                    imma16832(accM[mi][n], A1f[mi], B1f[nj][hf], B1f[nj][hf + 2]);
                    imma16832(accC[mi][n], A1f[mi], B2f[nj][hf], B2f[nj][hf + 2]);
                    imma16832(accC[mi][n], A2f[mi], B1f[nj][hf], B1f[nj][hf + 2]);
                }
        }
        __syncthreads();
    }

    // epilogue: T' = sA[row] * sBw[c,col] * (main + cross/256)
    const int gid = lane >> 2, tq = lane & 3;
    const int row0 = mt * 128 + warp_m * 64 + gid;
    const int col0 = nt * 128 + warp_n * 32 + tq * 2;
    const float ics = 1.0f / 256.0f;
    #pragma unroll
    for (int n = 0; n < 4; n++) {
        int cg = col0 + n * 8;
        float w0 = __ldg(&g_sBw[c * FDIM + cg]);
        float w1 = __ldg(&g_sBw[c * FDIM + cg + 1]);
        #pragma unroll
        for (int mi = 0; mi < 4; mi++) {
            int r = row0 + mi * 16;
            float sa0 = __ldg(&g_sA[r]);
            float sa1 = __ldg(&g_sA[r + 8]);
            float* o0 = g_T + ((size_t)c * N_ENT + r) * FDIM + cg;
            float* o1 = g_T + ((size_t)c * N_ENT + r + 8) * FDIM + cg;
            float2 v0 = make_float2(
                sa0 * w0 * ((float)accM[mi][n][0] + (float)accC[mi][n][0] * ics),
                sa0 * w1 * ((float)accM[mi][n][1] + (float)accC[mi][n][1] * ics));
            float2 v1 = make_float2(
                sa1 * w0 * ((float)accM[mi][n][2] + (float)accC[mi][n][2] * ics),
                sa1 * w1 * ((float)accM[mi][n][3] + (float)accC[mi][n][3] * ics));
            *(float2*)o0 = v0;
            *(float2*)o1 = v1;
        }
    }
}

// ---------------- gather-dot: out[c,p] = dot(T'_c[i0,:], E[i1,:]) ----------------
__global__ void __launch_bounds__(256) gather_kernel(const int* __restrict__ index,
                                                     const float* __restrict__ emb,
                                                     float* __restrict__ out) {
    int gw = (blockIdx.x * blockDim.x + threadIdx.x) >> 5;
    int lane = threadIdx.x & 31;
    int p0 = gw * 2;
    int c = p0 / PAIRS, p = p0 - c * PAIRS;
    int2 ipA = __ldg((const int2*)index + (size_t)c * PAIRS + p);
    int2 ipB = __ldg((const int2*)index + (size_t)c * PAIRS + p + 1);
    const float4* aA = (const float4*)(g_T + ((size_t)c * N_ENT + ipA.x) * FDIM);
    const float4* bA = (const float4*)(emb + (size_t)ipA.y * FDIM);
    const float4* aB = (const float4*)(g_T + ((size_t)c * N_ENT + ipB.x) * FDIM);
    const float4* bB = (const float4*)(emb + (size_t)ipB.y * FDIM);
    float accA = 0.f, accB = 0.f;
    #pragma unroll
    for (int j = 0; j < 4; j++) {
        float4 xA = __ldg(aA + lane + j * 32);
        float4 yA = __ldg(bA + lane + j * 32);
        float4 xB = __ldg(aB + lane + j * 32);
        float4 yB = __ldg(bB + lane + j * 32);
        accA += xA.x * yA.x + xA.y * yA.y + xA.z * yA.z + xA.w * yA.w;
        accB += xB.x * yB.x + xB.y * yB.y + xB.z * yB.z + xB.w * yB.w;
    }
    #pragma unroll
    for (int o = 16; o; o >>= 1) {
        accA += __shfl_xor_sync(0xffffffffu, accA, o);
        accB += __shfl_xor_sync(0xffffffffu, accB, o);
    }
    if (lane == 0) {
        out[(size_t)c * PAIRS + p]     = accA;
        out[(size_t)c * PAIRS + p + 1] = accB;
    }
}

// ---------------- launch ----------------
extern "C" void kernel_launch(void* const* d_in, const int* in_sizes, int n_in,
                              void* d_out, int out_size) {
    const float* emb   = (const float*)d_in[0];   // [4096, 512] f32
    const int*   index = (const int*)d_in[1];     // [39, 8192, 2] i32
    const float* W     = (const float*)d_in[2];   // [512, 512] f32
    const float* wl    = (const float*)d_in[3];   // [39, 512] f32
    float* out = (float*)d_out;                   // [39, 8192] f32

    cudaFuncSetAttribute(gemm_kernel, cudaFuncAttributeMaxDynamicSharedMemorySize, GEMM_SMEM);

    prep_Wt<<<dim3(FDIM / 32, FDIM / 32), dim3(32, 32)>>>(W);
    prep_E_q<<<N_ENT, 128>>>(emb);
    prep_B_q<<<dim3(FDIM, CELLS), 128>>>(wl);
    gemm_kernel<<<dim3(N_ENT / 128, FDIM / 128, CELLS), 256, GEMM_SMEM>>>(wl);
    gather_kernel<<<(CELLS * PAIRS) / 16, 256>>>(index, emb, out);
}

// round 8
// speedup vs baseline: 2.9565x; 2.9565x over previous
#include <cuda_runtime.h>
#include <cuda_fp16.h>
#include <stdint.h>

#define N_ENT 4096
#define FDIM  512
#define CELLS 39
#define PAIRS 8192

// ---------------- scratch (device globals: allocation-free rule) ----------------
__device__ __half g_Eh[N_ENT * FDIM];                       // 4 MB   fp16(E)
__device__ __half g_Bh[(size_t)CELLS * FDIM * FDIM];        // 20 MB  fp16(wl*W*2^10)          [c][kout][n]
__device__ __half g_B2[(size_t)CELLS * FDIM * FDIM];        // 20 MB  fp16(residual, exact-ish) [c][kout][n]
__device__ float  g_T[(size_t)CELLS * N_ENT * FDIM];        // 327 MB T'_c = (E @ Wc) * wl[c,k]

// ---------------- small helpers ----------------
__device__ __forceinline__ uint32_t smem_to_u32(const void* p) {
    uint32_t a;
    asm("{ .reg .u64 t; cvta.to.shared.u64 t, %1; cvt.u32.u64 %0, t; }" : "=r"(a) : "l"(p));
    return a;
}
__device__ __forceinline__ void cp_async16(uint32_t dst, const void* src) {
    asm volatile("cp.async.cg.shared.global [%0], [%1], 16;" :: "r"(dst), "l"(src));
}
#define CP_COMMIT() asm volatile("cp.async.commit_group;" ::: "memory")
#define CP_WAIT(n)  asm volatile("cp.async.wait_group %0;" :: "n"(n) : "memory")

#define LDSM_X4(r, addr) \
    asm volatile("ldmatrix.sync.aligned.m8n8.x4.shared.b16 {%0,%1,%2,%3}, [%4];" \
        : "=r"((r)[0]), "=r"((r)[1]), "=r"((r)[2]), "=r"((r)[3]) : "r"(addr))

__device__ __forceinline__ void mma_f16(float* c, const uint32_t* a, uint32_t b0, uint32_t b1) {
    asm volatile("mma.sync.aligned.m16n8k16.row.col.f32.f16.f16.f32 "
                 "{%0,%1,%2,%3}, {%4,%5,%6,%7}, {%8,%9}, {%0,%1,%2,%3};"
                 : "+f"(c[0]), "+f"(c[1]), "+f"(c[2]), "+f"(c[3])
                 : "r"(a[0]), "r"(a[1]), "r"(a[2]), "r"(a[3]), "r"(b0), "r"(b1));
}

// ---------------- prep kernels ----------------
__global__ void prep_E(const float* __restrict__ emb) {
    for (int i = blockIdx.x * blockDim.x + threadIdx.x; i < N_ENT * FDIM; i += gridDim.x * blockDim.x)
        g_Eh[i] = __float2half(emb[i]);
}

// B10 = wl[c,n]*W[n,kout]*1024; Bh = fp16(B10); B2 = fp16(B10 - Bh)  (exact residual split)
__global__ void prep_B(const float* __restrict__ W, const float* __restrict__ wl) {
    __shared__ float sW[32][33];
    int tx = threadIdx.x, ty = threadIdx.y;
    int n0 = blockIdx.x * 32, k0 = blockIdx.y * 32;
    sW[ty][tx] = W[(n0 + ty) * FDIM + (k0 + tx)];   // coalesced read
    __syncthreads();
    float wv = sW[tx][ty];                           // = W[n0+tx][k0+ty]
    int oidx = (k0 + ty) * FDIM + (n0 + tx);
    for (int c = 0; c < CELLS; c++) {
        float v = 1024.f * wl[c * FDIM + n0 + tx] * wv;
        __half h = __float2half(v);
        __half l = __float2half(v - __half2float(h));
        g_Bh[(size_t)c * FDIM * FDIM + oidx] = h;    // coalesced write (tx fast)
        g_B2[(size_t)c * FDIM * FDIM + oidx] = l;
    }
}

// ---------------- GEMM: T'_c = (E @ Wc) * wl[c,:]  — fp16 2-pass, single accumulator -------
// acc = Eh@Bh + Eh@B2 ; both terms same scale (2^10) -> one fp32 acc set.
// CTA tile M=128, N=256, BK=64, 256 threads (8 warps 2Mx4N, warp tile 64x64).
// Dropped error: El@B ~ 2^-11.8 rel -> predicted rel_err ~2.5e-4.
#define BK          64
#define NKC         (FDIM / BK)       // 8 chunks
#define ROW_S       144
#define A_TILE      (128 * ROW_S)     // 18432
#define B_TILE      (256 * ROW_S)     // 36864
#define A_HI        0
#define B_HI        (A_TILE)
#define B_LO        (A_TILE + B_TILE)
#define BUF_BYTES   (A_TILE + 2 * B_TILE)   // 92160
#define GEMM_SMEM   (2 * BUF_BYTES)         // 184320

__device__ __forceinline__ void load_buf(uint32_t smem_u, int buf, int kc, int tid,
                                         const char* ea, const char* bh, const char* b2) {
    uint32_t dbase = smem_u + buf * BUF_BYTES;
    // A tile: 128 rows x 8 segs = 1024 vecs
    {
        const char* s = ea + (size_t)kc * (BK * 2);
        #pragma unroll
        for (int i = 0; i < 4; i++) {
            int v = i * 256 + tid;
            int row = v >> 3, seg = v & 7;
            cp_async16(dbase + A_HI + row * ROW_S + seg * 16,
                       s + (size_t)row * (FDIM * 2) + seg * 16);
        }
    }
    // B tiles: 256 rows x 8 segs = 2048 vecs each
    {
        const char* sB[2] = { bh, b2 };
        #pragma unroll
        for (int t = 0; t < 2; t++) {
            uint32_t dt = dbase + B_HI + t * B_TILE;
            const char* s = sB[t] + (size_t)kc * (BK * 2);
            #pragma unroll
            for (int i = 0; i < 8; i++) {
                int v = i * 256 + tid;
                int row = v >> 3, seg = v & 7;
                cp_async16(dt + row * ROW_S + seg * 16,
                           s + (size_t)row * (FDIM * 2) + seg * 16);
            }
        }
    }
}

__global__ void __launch_bounds__(256, 1)
gemm_kernel(const float* __restrict__ wl) {
    extern __shared__ char smem[];
    uint32_t smem_u = smem_to_u32(smem);

    const int tid = threadIdx.x;
    const int wid = tid >> 5, lane = tid & 31;
    const int warp_m = wid & 1;        // rows warp_m*64
    const int warp_n = wid >> 1;       // cols warp_n*64
    const int mt = blockIdx.x, nt = blockIdx.y, c = blockIdx.z;

    const char* ea = (const char*)g_Eh + (size_t)(mt * 128) * (FDIM * 2);
    const char* bh = (const char*)g_Bh + ((size_t)c * FDIM + nt * 256) * (FDIM * 2);
    const char* b2 = (const char*)g_B2 + ((size_t)c * FDIM + nt * 256) * (FDIM * 2);

    float acc[4][8][4];
    #pragma unroll
    for (int i = 0; i < 4; i++)
        #pragma unroll
        for (int j = 0; j < 8; j++)
            #pragma unroll
            for (int q = 0; q < 4; q++) acc[i][j][q] = 0.f;

    const int lr = lane & 15;          // ldmatrix row within 16-row group
    const int lcb = (lane >> 4) * 16;  // col-block byte offset (0 or 16)

    load_buf(smem_u, 0, 0, tid, ea, bh, b2);
    CP_COMMIT();

    for (int kc = 0; kc < NKC; kc++) {
        int buf = kc & 1;
        if (kc + 1 < NKC) {
            load_buf(smem_u, buf ^ 1, kc + 1, tid, ea, bh, b2);
            CP_COMMIT();
            CP_WAIT(1);
        } else {
            CP_WAIT(0);
        }
        __syncthreads();

        uint32_t base = smem_u + buf * BUF_BYTES;
        uint32_t aRow = base + A_HI + (warp_m * 64 + lr) * ROW_S + lcb;
        uint32_t bRow = base + B_HI + (warp_n * 64 + lr) * ROW_S + lcb;

        #pragma unroll
        for (int k16 = 0; k16 < BK / 16; k16++) {
            uint32_t ko = k16 * 32;    // 16 fp16 = 32B
            uint32_t ah[4][4], bhf[4][4], b2f[4][4];
            #pragma unroll
            for (int mi = 0; mi < 4; mi++)
                LDSM_X4(ah[mi], aRow + mi * (16 * ROW_S) + ko);
            #pragma unroll
            for (int nj = 0; nj < 4; nj++) {
                LDSM_X4(bhf[nj], bRow + nj * (16 * ROW_S) + ko);
                LDSM_X4(b2f[nj], bRow + B_TILE + nj * (16 * ROW_S) + ko);
            }
            #pragma unroll
            for (int mi = 0; mi < 4; mi++)
                #pragma unroll
                for (int n = 0; n < 8; n++) {
                    int nj = n >> 1, hf = n & 1;
                    mma_f16(acc[mi][n], ah[mi], bhf[nj][hf], bhf[nj][hf + 2]);
                    mma_f16(acc[mi][n], ah[mi], b2f[nj][hf], b2f[nj][hf + 2]);
                }
        }
        __syncthreads();
    }

    // epilogue: T = acc * 2^-10 * wl[c,kout]
    const int gid = lane >> 2, tq = lane & 3;
    const int row0 = mt * 128 + warp_m * 64 + gid;
    const int col0 = nt * 256 + warp_n * 64 + tq * 2;
    const float s_main = 1.0f / 1024.0f;
    #pragma unroll
    for (int n = 0; n < 8; n++) {
        int cg = col0 + n * 8;
        float w0 = __ldg(&wl[c * FDIM + cg]) * s_main;
        float w1 = __ldg(&wl[c * FDIM + cg + 1]) * s_main;
        #pragma unroll
        for (int mi = 0; mi < 4; mi++) {
            int r = row0 + mi * 16;
            float* o0 = g_T + ((size_t)c * N_ENT + r) * FDIM + cg;
            float* o1 = g_T + ((size_t)c * N_ENT + r + 8) * FDIM + cg;
            float2 v0 = make_float2(acc[mi][n][0] * w0, acc[mi][n][1] * w1);
            float2 v1 = make_float2(acc[mi][n][2] * w0, acc[mi][n][3] * w1);
            *(float2*)o0 = v0;
            *(float2*)o1 = v1;
        }
    }
}

// ---------------- gather-dot: out[c,p] = dot(T'_c[i0,:], E[i1,:]) ----------------
__global__ void __launch_bounds__(256) gather_kernel(const int* __restrict__ index,
                                                     const float* __restrict__ emb,
                                                     float* __restrict__ out) {
    int gw = (blockIdx.x * blockDim.x + threadIdx.x) >> 5;
    int lane = threadIdx.x & 31;
    int p0 = gw * 2;
    int c = p0 / PAIRS, p = p0 - c * PAIRS;
    int2 ipA = __ldg((const int2*)index + (size_t)c * PAIRS + p);
    int2 ipB = __ldg((const int2*)index + (size_t)c * PAIRS + p + 1);
    const float4* aA = (const float4*)(g_T + ((size_t)c * N_ENT + ipA.x) * FDIM);
    const float4* bA = (const float4*)(emb + (size_t)ipA.y * FDIM);
    const float4* aB = (const float4*)(g_T + ((size_t)c * N_ENT + ipB.x) * FDIM);
    const float4* bB = (const float4*)(emb + (size_t)ipB.y * FDIM);
    float accA = 0.f, accB = 0.f;
    #pragma unroll
    for (int j = 0; j < 4; j++) {
        float4 xA = __ldg(aA + lane + j * 32);
        float4 yA = __ldg(bA + lane + j * 32);
        float4 xB = __ldg(aB + lane + j * 32);
        float4 yB = __ldg(bB + lane + j * 32);
        accA += xA.x * yA.x + xA.y * yA.y + xA.z * yA.z + xA.w * yA.w;
        accB += xB.x * yB.x + xB.y * yB.y + xB.z * yB.z + xB.w * yB.w;
    }
    #pragma unroll
    for (int o = 16; o; o >>= 1) {
        accA += __shfl_xor_sync(0xffffffffu, accA, o);
        accB += __shfl_xor_sync(0xffffffffu, accB, o);
    }
    if (lane == 0) {
        out[(size_t)c * PAIRS + p]     = accA;
        out[(size_t)c * PAIRS + p + 1] = accB;
    }
}

// ---------------- launch ----------------
extern "C" void kernel_launch(void* const* d_in, const int* in_sizes, int n_in,
                              void* d_out, int out_size) {
    const float* emb   = (const float*)d_in[0];   // [4096, 512] f32
    const int*   index = (const int*)d_in[1];     // [39, 8192, 2] i32
    const float* W     = (const float*)d_in[2];   // [512, 512] f32
    const float* wl    = (const float*)d_in[3];   // [39, 512] f32
    float* out = (float*)d_out;                   // [39, 8192] f32

    cudaFuncSetAttribute(gemm_kernel, cudaFuncAttributeMaxDynamicSharedMemorySize, GEMM_SMEM);

    prep_E<<<1024, 256>>>(emb);
    prep_B<<<dim3(FDIM / 32, FDIM / 32), dim3(32, 32)>>>(W, wl);
    gemm_kernel<<<dim3(N_ENT / 128, FDIM / 256, CELLS), 256, GEMM_SMEM>>>(wl);
    gather_kernel<<<(CELLS * PAIRS) / 16, 256>>>(index, emb, out);
}

// round 9
// speedup vs baseline: 4.6677x; 1.5788x over previous
#include <cuda_runtime.h>
#include <cuda_fp16.h>
#include <stdint.h>

#define N_ENT 4096
#define FDIM  512
#define CELLS 39
#define PAIRS 8192

// ---------------- scratch (device globals: allocation-free rule) ----------------
__device__ __half g_Eh[N_ENT * FDIM];                       // 4 MB   fp16(E)
__device__ __half g_Bh[(size_t)CELLS * FDIM * FDIM];        // 20 MB  fp16(wl*W*2^10) [c][kout][n]
__device__ float  g_T[(size_t)CELLS * N_ENT * FDIM];        // 327 MB T'_c = (E @ Wc) * wl[c,k]

// ---------------- small helpers ----------------
__device__ __forceinline__ uint32_t smem_to_u32(const void* p) {
    uint32_t a;
    asm("{ .reg .u64 t; cvta.to.shared.u64 t, %1; cvt.u32.u64 %0, t; }" : "=r"(a) : "l"(p));
    return a;
}
__device__ __forceinline__ void cp_async16(uint32_t dst, const void* src) {
    asm volatile("cp.async.cg.shared.global [%0], [%1], 16;" :: "r"(dst), "l"(src));
}
#define CP_COMMIT() asm volatile("cp.async.commit_group;" ::: "memory")
#define CP_WAIT(n)  asm volatile("cp.async.wait_group %0;" :: "n"(n) : "memory")

#define LDSM_X4(r, addr) \
    asm volatile("ldmatrix.sync.aligned.m8n8.x4.shared.b16 {%0,%1,%2,%3}, [%4];" \
        : "=r"((r)[0]), "=r"((r)[1]), "=r"((r)[2]), "=r"((r)[3]) : "r"(addr))

__device__ __forceinline__ void mma_f16(float* c, const uint32_t* a, uint32_t b0, uint32_t b1) {
    asm volatile("mma.sync.aligned.m16n8k16.row.col.f32.f16.f16.f32 "
                 "{%0,%1,%2,%3}, {%4,%5,%6,%7}, {%8,%9}, {%0,%1,%2,%3};"
                 : "+f"(c[0]), "+f"(c[1]), "+f"(c[2]), "+f"(c[3])
                 : "r"(a[0]), "r"(a[1]), "r"(a[2]), "r"(a[3]), "r"(b0), "r"(b1));
}

// ---------------- prep kernels ----------------
__global__ void prep_E(const float* __restrict__ emb) {
    for (int i = blockIdx.x * blockDim.x + threadIdx.x; i < N_ENT * FDIM; i += gridDim.x * blockDim.x)
        g_Eh[i] = __float2half(emb[i]);
}

// Bh = fp16( wl[c,n]*W[n,kout]*1024 )  — transpose via smem tile
__global__ void prep_B(const float* __restrict__ W, const float* __restrict__ wl) {
    __shared__ float sW[32][33];
    int tx = threadIdx.x, ty = threadIdx.y;
    int n0 = blockIdx.x * 32, k0 = blockIdx.y * 32;
    sW[ty][tx] = W[(n0 + ty) * FDIM + (k0 + tx)];   // coalesced read
    __syncthreads();
    float wv = sW[tx][ty];                           // = W[n0+tx][k0+ty]
    int oidx = (k0 + ty) * FDIM + (n0 + tx);
    for (int c = 0; c < CELLS; c++) {
        float v = 1024.f * wl[c * FDIM + n0 + tx] * wv;
        g_Bh[(size_t)c * FDIM * FDIM + oidx] = __float2half(v);   // coalesced write
    }
}

// ---------------- GEMM: T'_c = (E @ Wc) * wl[c,:]  — fp16 single pass ----------------
// CTA tile M=128, N=256, BK=64, 256 threads (8 warps 2Mx4N, warp tile 64x64).
// Error: E-rounding + B-rounding, each calibrated at ~2.1e-4 -> ~2.9e-4 combined.
#define BK          64
#define NKC         (FDIM / BK)       // 8 chunks
#define ROW_S       144
#define A_TILE      (128 * ROW_S)     // 18432
#define B_TILE      (256 * ROW_S)     // 36864
#define A_OFF       0
#define B_OFF       (A_TILE)
#define BUF_BYTES   (A_TILE + B_TILE)       // 55296
#define GEMM_SMEM   (2 * BUF_BYTES)         // 110592

__device__ __forceinline__ void load_buf(uint32_t smem_u, int buf, int kc, int tid,
                                         const char* ea, const char* bh) {
    uint32_t dbase = smem_u + buf * BUF_BYTES;
    // A tile: 128 rows x 8 segs = 1024 vecs
    {
        const char* s = ea + (size_t)kc * (BK * 2);
        #pragma unroll
        for (int i = 0; i < 4; i++) {
            int v = i * 256 + tid;
            int row = v >> 3, seg = v & 7;
            cp_async16(dbase + A_OFF + row * ROW_S + seg * 16,
                       s + (size_t)row * (FDIM * 2) + seg * 16);
        }
    }
    // B tile: 256 rows x 8 segs = 2048 vecs
    {
        const char* s = bh + (size_t)kc * (BK * 2);
        #pragma unroll
        for (int i = 0; i < 8; i++) {
            int v = i * 256 + tid;
            int row = v >> 3, seg = v & 7;
            cp_async16(dbase + B_OFF + row * ROW_S + seg * 16,
                       s + (size_t)row * (FDIM * 2) + seg * 16);
        }
    }
}

__global__ void __launch_bounds__(256, 1)
gemm_kernel(const float* __restrict__ wl) {
    extern __shared__ char smem[];
    uint32_t smem_u = smem_to_u32(smem);

    const int tid = threadIdx.x;
    const int wid = tid >> 5, lane = tid & 31;
    const int warp_m = wid & 1;        // rows warp_m*64
    const int warp_n = wid >> 1;       // cols warp_n*64
    const int mt = blockIdx.x, nt = blockIdx.y, c = blockIdx.z;

    const char* ea = (const char*)g_Eh + (size_t)(mt * 128) * (FDIM * 2);
    const char* bh = (const char*)g_Bh + ((size_t)c * FDIM + nt * 256) * (FDIM * 2);

    float acc[4][8][4];
    #pragma unroll
    for (int i = 0; i < 4; i++)
        #pragma unroll
        for (int j = 0; j < 8; j++)
            #pragma unroll
            for (int q = 0; q < 4; q++) acc[i][j][q] = 0.f;

    const int lr = lane & 15;          // ldmatrix row within 16-row group
    const int lcb = (lane >> 4) * 16;  // col-block byte offset (0 or 16)

    load_buf(smem_u, 0, 0, tid, ea, bh);
    CP_COMMIT();

    for (int kc = 0; kc < NKC; kc++) {
        int buf = kc & 1;
        if (kc + 1 < NKC) {
            load_buf(smem_u, buf ^ 1, kc + 1, tid, ea, bh);
            CP_COMMIT();
            CP_WAIT(1);
        } else {
            CP_WAIT(0);
        }
        __syncthreads();

        uint32_t base = smem_u + buf * BUF_BYTES;
        uint32_t aRow = base + A_OFF + (warp_m * 64 + lr) * ROW_S + lcb;
        uint32_t bRow = base + B_OFF + (warp_n * 64 + lr) * ROW_S + lcb;

        #pragma unroll
        for (int k16 = 0; k16 < BK / 16; k16++) {
            uint32_t ko = k16 * 32;    // 16 fp16 = 32B
            uint32_t ah[4][4], bf[4][4];
            #pragma unroll
            for (int mi = 0; mi < 4; mi++)
                LDSM_X4(ah[mi], aRow + mi * (16 * ROW_S) + ko);
            #pragma unroll
            for (int nj = 0; nj < 4; nj++)
                LDSM_X4(bf[nj], bRow + nj * (16 * ROW_S) + ko);
            #pragma unroll
            for (int mi = 0; mi < 4; mi++)
                #pragma unroll
                for (int n = 0; n < 8; n++) {
                    int nj = n >> 1, hf = n & 1;
                    mma_f16(acc[mi][n], ah[mi], bf[nj][hf], bf[nj][hf + 2]);
                }
        }
        __syncthreads();
    }

    // epilogue: T = acc * 2^-10 * wl[c,kout]
    const int gid = lane >> 2, tq = lane & 3;
    const int row0 = mt * 128 + warp_m * 64 + gid;
    const int col0 = nt * 256 + warp_n * 64 + tq * 2;
    const float s_main = 1.0f / 1024.0f;
    #pragma unroll
    for (int n = 0; n < 8; n++) {
        int cg = col0 + n * 8;
        float w0 = __ldg(&wl[c * FDIM + cg]) * s_main;
        float w1 = __ldg(&wl[c * FDIM + cg + 1]) * s_main;
        #pragma unroll
        for (int mi = 0; mi < 4; mi++) {
            int r = row0 + mi * 16;
            float* o0 = g_T + ((size_t)c * N_ENT + r) * FDIM + cg;
            float* o1 = g_T + ((size_t)c * N_ENT + r + 8) * FDIM + cg;
            float2 v0 = make_float2(acc[mi][n][0] * w0, acc[mi][n][1] * w1);
            float2 v1 = make_float2(acc[mi][n][2] * w0, acc[mi][n][3] * w1);
            *(float2*)o0 = v0;
            *(float2*)o1 = v1;
        }
    }
}

// ---------------- gather-dot: out[c,p] = dot(T'_c[i0,:], E[i1,:]) ----------------
__global__ void __launch_bounds__(256) gather_kernel(const int* __restrict__ index,
                                                     const float* __restrict__ emb,
                                                     float* __restrict__ out) {
    int gw = (blockIdx.x * blockDim.x + threadIdx.x) >> 5;
    int lane = threadIdx.x & 31;
    int p0 = gw * 2;
    int c = p0 / PAIRS, p = p0 - c * PAIRS;
    int2 ipA = __ldg((const int2*)index + (size_t)c * PAIRS + p);
    int2 ipB = __ldg((const int2*)index + (size_t)c * PAIRS + p + 1);
    const float4* aA = (const float4*)(g_T + ((size_t)c * N_ENT + ipA.x) * FDIM);
    const float4* bA = (const float4*)(emb + (size_t)ipA.y * FDIM);
    const float4* aB = (const float4*)(g_T + ((size_t)c * N_ENT + ipB.x) * FDIM);
    const float4* bB = (const float4*)(emb + (size_t)ipB.y * FDIM);
    float accA = 0.f, accB = 0.f;
    #pragma unroll
    for (int j = 0; j < 4; j++) {
        float4 xA = __ldg(aA + lane + j * 32);
        float4 yA = __ldg(bA + lane + j * 32);
        float4 xB = __ldg(aB + lane + j * 32);
        float4 yB = __ldg(bB + lane + j * 32);
        accA += xA.x * yA.x + xA.y * yA.y + xA.z * yA.z + xA.w * yA.w;
        accB += xB.x * yB.x + xB.y * yB.y + xB.z * yB.z + xB.w * yB.w;
    }
    #pragma unroll
    for (int o = 16; o; o >>= 1) {
        accA += __shfl_xor_sync(0xffffffffu, accA, o);
        accB += __shfl_xor_sync(0xffffffffu, accB, o);
    }
    if (lane == 0) {
        out[(size_t)c * PAIRS + p]     = accA;
        out[(size_t)c * PAIRS + p + 1] = accB;
    }
}

// ---------------- launch ----------------
extern "C" void kernel_launch(void* const* d_in, const int* in_sizes, int n_in,
                              void* d_out, int out_size) {
    const float* emb   = (const float*)d_in[0];   // [4096, 512] f32
    const int*   index = (const int*)d_in[1];     // [39, 8192, 2] i32
    const float* W     = (const float*)d_in[2];   // [512, 512] f32
    const float* wl    = (const float*)d_in[3];   // [39, 512] f32
    float* out = (float*)d_out;                   // [39, 8192] f32

    cudaFuncSetAttribute(gemm_kernel, cudaFuncAttributeMaxDynamicSharedMemorySize, GEMM_SMEM);

    prep_E<<<1024, 256>>>(emb);
    prep_B<<<dim3(FDIM / 32, FDIM / 32), dim3(32, 32)>>>(W, wl);
    gemm_kernel<<<dim3(N_ENT / 128, FDIM / 256, CELLS), 256, GEMM_SMEM>>>(wl);
    gather_kernel<<<(CELLS * PAIRS) / 16, 256>>>(index, emb, out);
}

// round 10
// speedup vs baseline: 4.9252x; 1.0552x over previous
#include <cuda_runtime.h>
#include <cuda_fp16.h>
#include <stdint.h>

#define N_ENT 4096
#define FDIM  512
#define CELLS 39
#define PAIRS 8192

// ---------------- scratch (device globals: allocation-free rule) ----------------
__device__ __half g_Eh[N_ENT * FDIM];                       // 4 MB   fp16(E)
__device__ __half g_Bh[(size_t)CELLS * FDIM * FDIM];        // 20 MB  fp16(wl*W*2^10) [c][kout][n]
__device__ __half g_T[(size_t)CELLS * N_ENT * FDIM];        // 163 MB fp16( T'_c * 2^6 )

// ---------------- small helpers ----------------
__device__ __forceinline__ uint32_t smem_to_u32(const void* p) {
    uint32_t a;
    asm("{ .reg .u64 t; cvta.to.shared.u64 t, %1; cvt.u32.u64 %0, t; }" : "=r"(a) : "l"(p));
    return a;
}
__device__ __forceinline__ void cp_async16(uint32_t dst, const void* src) {
    asm volatile("cp.async.cg.shared.global [%0], [%1], 16;" :: "r"(dst), "l"(src));
}
#define CP_COMMIT() asm volatile("cp.async.commit_group;" ::: "memory")
#define CP_WAIT(n)  asm volatile("cp.async.wait_group %0;" :: "n"(n) : "memory")

#define LDSM_X4(r, addr) \
    asm volatile("ldmatrix.sync.aligned.m8n8.x4.shared.b16 {%0,%1,%2,%3}, [%4];" \
        : "=r"((r)[0]), "=r"((r)[1]), "=r"((r)[2]), "=r"((r)[3]) : "r"(addr))

__device__ __forceinline__ void mma_f16(float* c, const uint32_t* a, uint32_t b0, uint32_t b1) {
    asm volatile("mma.sync.aligned.m16n8k16.row.col.f32.f16.f16.f32 "
                 "{%0,%1,%2,%3}, {%4,%5,%6,%7}, {%8,%9}, {%0,%1,%2,%3};"
                 : "+f"(c[0]), "+f"(c[1]), "+f"(c[2]), "+f"(c[3])
                 : "r"(a[0]), "r"(a[1]), "r"(a[2]), "r"(a[3]), "r"(b0), "r"(b1));
}

// ---------------- prep kernels ----------------
__global__ void prep_E(const float* __restrict__ emb) {
    for (int i = blockIdx.x * blockDim.x + threadIdx.x; i < N_ENT * FDIM; i += gridDim.x * blockDim.x)
        g_Eh[i] = __float2half(emb[i]);
}

// Bh = fp16( wl[c,n]*W[n,kout]*1024 )  — transpose via smem tile
__global__ void prep_B(const float* __restrict__ W, const float* __restrict__ wl) {
    __shared__ float sW[32][33];
    int tx = threadIdx.x, ty = threadIdx.y;
    int n0 = blockIdx.x * 32, k0 = blockIdx.y * 32;
    sW[ty][tx] = W[(n0 + ty) * FDIM + (k0 + tx)];   // coalesced read
    __syncthreads();
    float wv = sW[tx][ty];                           // = W[n0+tx][k0+ty]
    int oidx = (k0 + ty) * FDIM + (n0 + tx);
    for (int c = 0; c < CELLS; c++) {
        float v = 1024.f * wl[c * FDIM + n0 + tx] * wv;
        g_Bh[(size_t)c * FDIM * FDIM + oidx] = __float2half(v);   // coalesced write
    }
}

// ---------------- GEMM: T'_c = (E @ Wc) * wl[c,:]  — fp16 single pass, fp16 output ------
// CTA tile M=128, N=256, BK=64, 256 threads (8 warps 2Mx4N, warp tile 64x64).
// Output scaled by 2^6 to center fp16 range: T elements ~|0.3|, *64 ~ |20|.
#define BK          64
#define NKC         (FDIM / BK)       // 8 chunks
#define ROW_S       144
#define A_TILE      (128 * ROW_S)     // 18432
#define B_TILE      (256 * ROW_S)     // 36864
#define A_OFF       0
#define B_OFF       (A_TILE)
#define BUF_BYTES   (A_TILE + B_TILE)       // 55296
#define GEMM_SMEM   (2 * BUF_BYTES)         // 110592

__device__ __forceinline__ void load_buf(uint32_t smem_u, int buf, int kc, int tid,
                                         const char* ea, const char* bh) {
    uint32_t dbase = smem_u + buf * BUF_BYTES;
    {
        const char* s = ea + (size_t)kc * (BK * 2);
        #pragma unroll
        for (int i = 0; i < 4; i++) {
            int v = i * 256 + tid;
            int row = v >> 3, seg = v & 7;
            cp_async16(dbase + A_OFF + row * ROW_S + seg * 16,
                       s + (size_t)row * (FDIM * 2) + seg * 16);
        }
    }
    {
        const char* s = bh + (size_t)kc * (BK * 2);
        #pragma unroll
        for (int i = 0; i < 8; i++) {
            int v = i * 256 + tid;
            int row = v >> 3, seg = v & 7;
            cp_async16(dbase + B_OFF + row * ROW_S + seg * 16,
                       s + (size_t)row * (FDIM * 2) + seg * 16);
        }
    }
}

__global__ void __launch_bounds__(256, 1)
gemm_kernel(const float* __restrict__ wl) {
    extern __shared__ char smem[];
    uint32_t smem_u = smem_to_u32(smem);

    const int tid = threadIdx.x;
    const int wid = tid >> 5, lane = tid & 31;
    const int warp_m = wid & 1;        // rows warp_m*64
    const int warp_n = wid >> 1;       // cols warp_n*64
    const int mt = blockIdx.x, nt = blockIdx.y, c = blockIdx.z;

    const char* ea = (const char*)g_Eh + (size_t)(mt * 128) * (FDIM * 2);
    const char* bh = (const char*)g_Bh + ((size_t)c * FDIM + nt * 256) * (FDIM * 2);

    float acc[4][8][4];
    #pragma unroll
    for (int i = 0; i < 4; i++)
        #pragma unroll
        for (int j = 0; j < 8; j++)
            #pragma unroll
            for (int q = 0; q < 4; q++) acc[i][j][q] = 0.f;

    const int lr = lane & 15;          // ldmatrix row within 16-row group
    const int lcb = (lane >> 4) * 16;  // col-block byte offset (0 or 16)

    load_buf(smem_u, 0, 0, tid, ea, bh);
    CP_COMMIT();

    for (int kc = 0; kc < NKC; kc++) {
        int buf = kc & 1;
        if (kc + 1 < NKC) {
            load_buf(smem_u, buf ^ 1, kc + 1, tid, ea, bh);
            CP_COMMIT();
            CP_WAIT(1);
        } else {
            CP_WAIT(0);
        }
        __syncthreads();

        uint32_t base = smem_u + buf * BUF_BYTES;
        uint32_t aRow = base + A_OFF + (warp_m * 64 + lr) * ROW_S + lcb;
        uint32_t bRow = base + B_OFF + (warp_n * 64 + lr) * ROW_S + lcb;

        #pragma unroll
        for (int k16 = 0; k16 < BK / 16; k16++) {
            uint32_t ko = k16 * 32;    // 16 fp16 = 32B
            uint32_t ah[4][4], bf[4][4];
            #pragma unroll
            for (int mi = 0; mi < 4; mi++)
                LDSM_X4(ah[mi], aRow + mi * (16 * ROW_S) + ko);
            #pragma unroll
            for (int nj = 0; nj < 4; nj++)
                LDSM_X4(bf[nj], bRow + nj * (16 * ROW_S) + ko);
            #pragma unroll
            for (int mi = 0; mi < 4; mi++)
                #pragma unroll
                for (int n = 0; n < 8; n++) {
                    int nj = n >> 1, hf = n & 1;
                    mma_f16(acc[mi][n], ah[mi], bf[nj][hf], bf[nj][hf + 2]);
                }
        }
        __syncthreads();
    }

    // epilogue: T16 = fp16( acc * 2^-10 * wl[c,kout] * 2^6 )
    const int gid = lane >> 2, tq = lane & 3;
    const int row0 = mt * 128 + warp_m * 64 + gid;
    const int col0 = nt * 256 + warp_n * 64 + tq * 2;
    const float s_main = 64.0f / 1024.0f;     // 2^-10 * 2^6
    #pragma unroll
    for (int n = 0; n < 8; n++) {
        int cg = col0 + n * 8;
        float w0 = __ldg(&wl[c * FDIM + cg]) * s_main;
        float w1 = __ldg(&wl[c * FDIM + cg + 1]) * s_main;
        #pragma unroll
        for (int mi = 0; mi < 4; mi++) {
            int r = row0 + mi * 16;
            __half* o0 = g_T + ((size_t)c * N_ENT + r) * FDIM + cg;
            __half* o1 = g_T + ((size_t)c * N_ENT + r + 8) * FDIM + cg;
            *(__half2*)o0 = __floats2half2_rn(acc[mi][n][0] * w0, acc[mi][n][1] * w1);
            *(__half2*)o1 = __floats2half2_rn(acc[mi][n][2] * w0, acc[mi][n][3] * w1);
        }
    }
}

// ---------------- gather-dot: out[c,p] = 2^-6 * dot(T16_c[i0,:], Eh[i1,:]) --------------
// fp16 rows: 1 KB each. 2 pairs per warp, 2 uint4 per lane per row -> 8 ldg.128/lane.
__global__ void __launch_bounds__(256) gather_kernel(const int* __restrict__ index,
                                                     float* __restrict__ out) {
    int gw = (blockIdx.x * blockDim.x + threadIdx.x) >> 5;
    int lane = threadIdx.x & 31;
    int p0 = gw * 2;
    int c = p0 / PAIRS, p = p0 - c * PAIRS;
    int2 ipA = __ldg((const int2*)index + (size_t)c * PAIRS + p);
    int2 ipB = __ldg((const int2*)index + (size_t)c * PAIRS + p + 1);
    const uint4* aA = (const uint4*)(g_T + ((size_t)c * N_ENT + ipA.x) * FDIM);
    const uint4* bA = (const uint4*)(g_Eh + (size_t)ipA.y * FDIM);
    const uint4* aB = (const uint4*)(g_T + ((size_t)c * N_ENT + ipB.x) * FDIM);
    const uint4* bB = (const uint4*)(g_Eh + (size_t)ipB.y * FDIM);
    float accA = 0.f, accB = 0.f;
    #pragma unroll
    for (int j = 0; j < 2; j++) {     // 64 uint4 per row / 32 lanes
        uint4 xA = __ldg(aA + lane + j * 32);
        uint4 yA = __ldg(bA + lane + j * 32);
        uint4 xB = __ldg(aB + lane + j * 32);
        uint4 yB = __ldg(bB + lane + j * 32);
        const uint32_t* xa = (const uint32_t*)&xA;
        const uint32_t* ya = (const uint32_t*)&yA;
        const uint32_t* xb = (const uint32_t*)&xB;
        const uint32_t* yb = (const uint32_t*)&yB;
        #pragma unroll
        for (int q = 0; q < 4; q++) {
            float2 fxa = __half22float2(*(const __half2*)&xa[q]);
            float2 fya = __half22float2(*(const __half2*)&ya[q]);
            float2 fxb = __half22float2(*(const __half2*)&xb[q]);
            float2 fyb = __half22float2(*(const __half2*)&yb[q]);
            accA += fxa.x * fya.x + fxa.y * fya.y;
            accB += fxb.x * fyb.x + fxb.y * fyb.y;
        }
    }
    #pragma unroll
    for (int o = 16; o; o >>= 1) {
        accA += __shfl_xor_sync(0xffffffffu, accA, o);
        accB += __shfl_xor_sync(0xffffffffu, accB, o);
    }
    if (lane == 0) {
        const float s = 1.0f / 64.0f;   // undo 2^6 on T
        out[(size_t)c * PAIRS + p]     = accA * s;
        out[(size_t)c * PAIRS + p + 1] = accB * s;
    }
}

// ---------------- launch ----------------
extern "C" void kernel_launch(void* const* d_in, const int* in_sizes, int n_in,
                              void* d_out, int out_size) {
    const float* emb   = (const float*)d_in[0];   // [4096, 512] f32
    const int*   index = (const int*)d_in[1];     // [39, 8192, 2] i32
    const float* W     = (const float*)d_in[2];   // [512, 512] f32
    const float* wl    = (const float*)d_in[3];   // [39, 512] f32
    float* out = (float*)d_out;                   // [39, 8192] f32

    cudaFuncSetAttribute(gemm_kernel, cudaFuncAttributeMaxDynamicSharedMemorySize, GEMM_SMEM);

    prep_E<<<1024, 256>>>(emb);
    prep_B<<<dim3(FDIM / 32, FDIM / 32), dim3(32, 32)>>>(W, wl);
    gemm_kernel<<<dim3(N_ENT / 128, FDIM / 256, CELLS), 256, GEMM_SMEM>>>(wl);
    gather_kernel<<<(CELLS * PAIRS) / 16, 256>>>(index, out);
}

// round 11
// speedup vs baseline: 5.2325x; 1.0624x over previous
#include <cuda_runtime.h>
#include <cuda_fp16.h>
#include <stdint.h>

#define N_ENT 4096
#define FDIM  512
#define CELLS 39
#define PAIRS 8192

// ---------------- scratch (device globals: allocation-free rule) ----------------
__device__ __half g_Eh[N_ENT * FDIM];                       // 4 MB   fp16(E)
__device__ __half g_Bh[(size_t)CELLS * FDIM * FDIM];        // 20 MB  fp16(wl*W*2^10) [c][kout][n]
__device__ __half g_T[(size_t)CELLS * N_ENT * FDIM];        // 163 MB fp16( T'_c * 2^6 ), compacted rows
__device__ int    g_list[CELLS * N_ENT];                    // compact row -> entity id
__device__ int    g_map[CELLS * N_ENT];                     // entity id -> compact row
__device__ int    g_cnt[CELLS];                             // distinct i0 count per cell

// ---------------- small helpers ----------------
__device__ __forceinline__ uint32_t smem_to_u32(const void* p) {
    uint32_t a;
    asm("{ .reg .u64 t; cvta.to.shared.u64 t, %1; cvt.u32.u64 %0, t; }" : "=r"(a) : "l"(p));
    return a;
}
__device__ __forceinline__ void cp_async16(uint32_t dst, const void* src) {
    asm volatile("cp.async.cg.shared.global [%0], [%1], 16;" :: "r"(dst), "l"(src));
}
#define CP_COMMIT() asm volatile("cp.async.commit_group;" ::: "memory")
#define CP_WAIT(n)  asm volatile("cp.async.wait_group %0;" :: "n"(n) : "memory")

#define LDSM_X4(r, addr) \
    asm volatile("ldmatrix.sync.aligned.m8n8.x4.shared.b16 {%0,%1,%2,%3}, [%4];" \
        : "=r"((r)[0]), "=r"((r)[1]), "=r"((r)[2]), "=r"((r)[3]) : "r"(addr))

__device__ __forceinline__ void mma_f16(float* c, const uint32_t* a, uint32_t b0, uint32_t b1) {
    asm volatile("mma.sync.aligned.m16n8k16.row.col.f32.f16.f16.f32 "
                 "{%0,%1,%2,%3}, {%4,%5,%6,%7}, {%8,%9}, {%0,%1,%2,%3};"
                 : "+f"(c[0]), "+f"(c[1]), "+f"(c[2]), "+f"(c[3])
                 : "r"(a[0]), "r"(a[1]), "r"(a[2]), "r"(a[3]), "r"(b0), "r"(b1));
}

// ---------------- prep kernels ----------------
__global__ void prep_E(const float* __restrict__ emb) {
    for (int i = blockIdx.x * blockDim.x + threadIdx.x; i < N_ENT * FDIM; i += gridDim.x * blockDim.x)
        g_Eh[i] = __float2half(emb[i]);
}

// Bh = fp16( wl[c,n]*W[n,kout]*1024 )  — transpose via smem tile
__global__ void prep_B(const float* __restrict__ W, const float* __restrict__ wl) {
    __shared__ float sW[32][33];
    int tx = threadIdx.x, ty = threadIdx.y;
    int n0 = blockIdx.x * 32, k0 = blockIdx.y * 32;
    sW[ty][tx] = W[(n0 + ty) * FDIM + (k0 + tx)];
    __syncthreads();
    float wv = sW[tx][ty];
    int oidx = (k0 + ty) * FDIM + (n0 + tx);
    for (int c = 0; c < CELLS; c++) {
        float v = 1024.f * wl[c * FDIM + n0 + tx] * wv;
        g_Bh[(size_t)c * FDIM * FDIM + oidx] = __float2half(v);
    }
}

// per-cell distinct-i0 compaction: flags + block scan. One block per cell, 1024 threads.
__global__ void __launch_bounds__(1024) compact_kernel(const int* __restrict__ index) {
    int c = blockIdx.x, t = threadIdx.x;
    __shared__ unsigned char flags[N_ENT];
    __shared__ int wsum[32];
    #pragma unroll
    for (int i = t; i < N_ENT; i += 1024) flags[i] = 0;
    __syncthreads();
    for (int p = t; p < PAIRS; p += 1024)
        flags[index[((size_t)c * PAIRS + p) * 2]] = 1;  // races benign (same value)
    __syncthreads();
    int f[4], s = 0;
    #pragma unroll
    for (int j = 0; j < 4; j++) { f[j] = flags[t * 4 + j]; s += f[j]; }
    int lane = t & 31, wid = t >> 5;
    int sc = s;
    #pragma unroll
    for (int o = 1; o < 32; o <<= 1) {
        int v = __shfl_up_sync(0xffffffffu, sc, o);
        if (lane >= o) sc += v;
    }
    if (lane == 31) wsum[wid] = sc;
    __syncthreads();
    if (wid == 0) {
        int v = wsum[lane];
        #pragma unroll
        for (int o = 1; o < 32; o <<= 1) {
            int u = __shfl_up_sync(0xffffffffu, v, o);
            if (lane >= o) v += u;
        }
        wsum[lane] = v;   // inclusive scan of warp totals
    }
    __syncthreads();
    int base = (wid > 0 ? wsum[wid - 1] : 0) + (sc - s);   // exclusive prefix for this thread
    #pragma unroll
    for (int j = 0; j < 4; j++) {
        if (f[j]) {
            int i = t * 4 + j;
            g_map[c * N_ENT + i] = base;
            g_list[c * N_ENT + base] = i;
            base++;
        }
    }
    if (t == 1023) g_cnt[c] = wsum[31];
}

// ---------------- GEMM: compacted-M fp16 single pass, fp16 output ----------------
// CTA tile M=128, N=256, BK=64, 256 threads (8 warps 2Mx4N, warp tile 64x64).
#define BK          64
#define NKC         (FDIM / BK)       // 8 chunks
#define ROW_S       144
#define A_TILE      (128 * ROW_S)
#define B_TILE      (256 * ROW_S)
#define A_OFF       0
#define B_OFF       (A_TILE)
#define BUF_BYTES   (A_TILE + B_TILE)       // 55296
#define GEMM_SMEM   (2 * BUF_BYTES)         // 110592

__device__ __forceinline__ void load_buf(uint32_t smem_u, int buf, int kc, int tid,
                                         const int* srow, const char* bh) {
    uint32_t dbase = smem_u + buf * BUF_BYTES;
    // A tile: indirect rows via srow
    {
        #pragma unroll
        for (int i = 0; i < 4; i++) {
            int v = i * 256 + tid;
            int row = v >> 3, seg = v & 7;
            const char* s = (const char*)g_Eh + (size_t)srow[row] * (FDIM * 2)
                            + (size_t)kc * (BK * 2) + seg * 16;
            cp_async16(dbase + A_OFF + row * ROW_S + seg * 16, s);
        }
    }
    // B tile: 256 rows
    {
        const char* s = bh + (size_t)kc * (BK * 2);
        #pragma unroll
        for (int i = 0; i < 8; i++) {
            int v = i * 256 + tid;
            int row = v >> 3, seg = v & 7;
            cp_async16(dbase + B_OFF + row * ROW_S + seg * 16,
                       s + (size_t)row * (FDIM * 2) + seg * 16);
        }
    }
}

__global__ void __launch_bounds__(256, 1)
gemm_kernel(const float* __restrict__ wl) {
    extern __shared__ char smem[];
    __shared__ int srow[128];
    uint32_t smem_u = smem_to_u32(smem);

    const int tid = threadIdx.x;
    const int wid = tid >> 5, lane = tid & 31;
    const int warp_m = wid & 1;
    const int warp_n = wid >> 1;
    const int mt = blockIdx.x, nt = blockIdx.y, c = blockIdx.z;

    const int cnt = __ldg(&g_cnt[c]);
    if (mt * 128 >= cnt) return;                 // whole CTA exits together

    if (tid < 128) {
        int r = mt * 128 + tid;
        srow[tid] = __ldg(&g_list[c * N_ENT + (r < cnt ? r : mt * 128)]);
    }
    __syncthreads();

    const char* bh = (const char*)g_Bh + ((size_t)c * FDIM + nt * 256) * (FDIM * 2);

    float acc[4][8][4];
    #pragma unroll
    for (int i = 0; i < 4; i++)
        #pragma unroll
        for (int j = 0; j < 8; j++)
            #pragma unroll
            for (int q = 0; q < 4; q++) acc[i][j][q] = 0.f;

    const int lr = lane & 15;
    const int lcb = (lane >> 4) * 16;

    load_buf(smem_u, 0, 0, tid, srow, bh);
    CP_COMMIT();

    for (int kc = 0; kc < NKC; kc++) {
        int buf = kc & 1;
        if (kc + 1 < NKC) {
            load_buf(smem_u, buf ^ 1, kc + 1, tid, srow, bh);
            CP_COMMIT();
            CP_WAIT(1);
        } else {
            CP_WAIT(0);
        }
        __syncthreads();

        uint32_t base = smem_u + buf * BUF_BYTES;
        uint32_t aRow = base + A_OFF + (warp_m * 64 + lr) * ROW_S + lcb;
        uint32_t bRow = base + B_OFF + (warp_n * 64 + lr) * ROW_S + lcb;

        #pragma unroll
        for (int k16 = 0; k16 < BK / 16; k16++) {
            uint32_t ko = k16 * 32;
            uint32_t ah[4][4], bf[4][4];
            #pragma unroll
            for (int mi = 0; mi < 4; mi++)
                LDSM_X4(ah[mi], aRow + mi * (16 * ROW_S) + ko);
            #pragma unroll
            for (int nj = 0; nj < 4; nj++)
                LDSM_X4(bf[nj], bRow + nj * (16 * ROW_S) + ko);
            #pragma unroll
            for (int mi = 0; mi < 4; mi++)
                #pragma unroll
                for (int n = 0; n < 8; n++) {
                    int nj = n >> 1, hf = n & 1;
                    mma_f16(acc[mi][n], ah[mi], bf[nj][hf], bf[nj][hf + 2]);
                }
        }
        __syncthreads();
    }

    // epilogue: T16[compact row] = fp16( acc * 2^-10 * wl[c,kout] * 2^6 )
    const int gid = lane >> 2, tq = lane & 3;
    const int row0 = mt * 128 + warp_m * 64 + gid;
    const int col0 = nt * 256 + warp_n * 64 + tq * 2;
    const float s_main = 64.0f / 1024.0f;
    #pragma unroll
    for (int n = 0; n < 8; n++) {
        int cg = col0 + n * 8;
        float w0 = __ldg(&wl[c * FDIM + cg]) * s_main;
        float w1 = __ldg(&wl[c * FDIM + cg + 1]) * s_main;
        #pragma unroll
        for (int mi = 0; mi < 4; mi++) {
            int r = row0 + mi * 16;
            __half* o0 = g_T + ((size_t)c * N_ENT + r) * FDIM + cg;
            __half* o1 = g_T + ((size_t)c * N_ENT + r + 8) * FDIM + cg;
            *(__half2*)o0 = __floats2half2_rn(acc[mi][n][0] * w0, acc[mi][n][1] * w1);
            *(__half2*)o1 = __floats2half2_rn(acc[mi][n][2] * w0, acc[mi][n][3] * w1);
        }
    }
}

// ---------------- gather-dot: out[c,p] = 2^-6 * dot(T16_c[map[i0],:], Eh[i1,:]) ---------
// 4 pairs per warp -> 16 ldg.128/lane in flight.
__global__ void __launch_bounds__(256) gather_kernel(const int* __restrict__ index,
                                                     float* __restrict__ out) {
    int gw = (blockIdx.x * blockDim.x + threadIdx.x) >> 5;
    int lane = threadIdx.x & 31;
    int p0 = gw * 4;
    int c = p0 / PAIRS, p = p0 - c * PAIRS;   // PAIRS % 4 == 0 -> same cell
    const uint4* ta[4];
    const uint4* tb[4];
    #pragma unroll
    for (int u = 0; u < 4; u++) {
        int2 ip = __ldg((const int2*)index + (size_t)c * PAIRS + p + u);
        int r0 = __ldg(&g_map[c * N_ENT + ip.x]);
        ta[u] = (const uint4*)(g_T + ((size_t)c * N_ENT + r0) * FDIM);
        tb[u] = (const uint4*)(g_Eh + (size_t)ip.y * FDIM);
    }
    float acc[4] = {0.f, 0.f, 0.f, 0.f};
    #pragma unroll
    for (int j = 0; j < 2; j++) {
        #pragma unroll
        for (int u = 0; u < 4; u++) {
            uint4 x = __ldg(ta[u] + lane + j * 32);
            uint4 y = __ldg(tb[u] + lane + j * 32);
            const uint32_t* xa = (const uint32_t*)&x;
            const uint32_t* ya = (const uint32_t*)&y;
            #pragma unroll
            for (int q = 0; q < 4; q++) {
                float2 fx = __half22float2(*(const __half2*)&xa[q]);
                float2 fy = __half22float2(*(const __half2*)&ya[q]);
                acc[u] += fx.x * fy.x + fx.y * fy.y;
            }
        }
    }
    #pragma unroll
    for (int o = 16; o; o >>= 1)
        #pragma unroll
        for (int u = 0; u < 4; u++)
            acc[u] += __shfl_xor_sync(0xffffffffu, acc[u], o);
    if (lane == 0) {
        const float s = 1.0f / 64.0f;
        #pragma unroll
        for (int u = 0; u < 4; u++)
            out[(size_t)c * PAIRS + p + u] = acc[u] * s;
    }
}

// ---------------- launch ----------------
extern "C" void kernel_launch(void* const* d_in, const int* in_sizes, int n_in,
                              void* d_out, int out_size) {
    const float* emb   = (const float*)d_in[0];   // [4096, 512] f32
    const int*   index = (const int*)d_in[1];     // [39, 8192, 2] i32
    const float* W     = (const float*)d_in[2];   // [512, 512] f32
    const float* wl    = (const float*)d_in[3];   // [39, 512] f32
    float* out = (float*)d_out;                   // [39, 8192] f32

    cudaFuncSetAttribute(gemm_kernel, cudaFuncAttributeMaxDynamicSharedMemorySize, GEMM_SMEM);

    prep_E<<<1024, 256>>>(emb);
    prep_B<<<dim3(FDIM / 32, FDIM / 32), dim3(32, 32)>>>(W, wl);
    compact_kernel<<<CELLS, 1024>>>(index);
    gemm_kernel<<<dim3(N_ENT / 128, FDIM / 256, CELLS), 256, GEMM_SMEM>>>(wl);
    gather_kernel<<<(CELLS * PAIRS) / 32, 256>>>(index, out);
}